// round 1
// baseline (speedup 1.0000x reference)
#include <cuda_runtime.h>

// Problem constants
#define B_DIM 64
#define S_DIM 512
#define W_DIM 256
#define D_DIM 768
#define N_DIM 96      // A*3
#define KT 32         // K tile
#define MT 64         // rows (w) per CTA
#define AS_STRIDE 36  // padded row stride (floats), 144B: 16B-aligned, low conflicts
#define BS_STRIDE 36

typedef unsigned long long ull;

__device__ __forceinline__ ull ffma2(ull a, ull b, ull c) {
    ull d;
    asm("fma.rn.f32x2 %0, %1, %2, %3;" : "=l"(d) : "l"(a), "l"(b), "l"(c));
    return d;
}

__device__ __forceinline__ void unpack2(ull v, float& lo, float& hi) {
    asm("mov.b64 {%0, %1}, %2;" : "=f"(lo), "=f"(hi) : "l"(v));
}

__global__ __launch_bounds__(256, 2)
void ner_gemm_kernel(const float* __restrict__ seq,
                     const int* __restrict__ widx,
                     const float* __restrict__ clsw,
                     const float* __restrict__ clsb,
                     float* __restrict__ out) {
    __shared__ __align__(16) float As[MT][AS_STRIDE];    // [row][k] fp32
    __shared__ __align__(16) float Bs[N_DIM][BS_STRIDE]; // [n][k]   fp32
    __shared__ int idx_s[MT];

    const int tid = threadIdx.x;
    const int b   = blockIdx.y;
    const int w0  = blockIdx.x * MT;
    const int tc  = tid & 15;   // maps to w rows (lane-minor -> coalesced stores)
    const int tr  = tid >> 4;   // maps to n cols

    if (tid < MT) idx_s[tid] = widx[b * W_DIM + w0 + tid];
    __syncthreads();

    // A-tile load tasks: 64 rows x 8 float4-chunks = 512 tasks, 2 per thread
    const int rowA0 = tid >> 3;         // 0..31
    const int rowA1 = rowA0 + 32;       // 32..63
    const int kcA   = (tid & 7) * 4;
    const float* aPtr0 = seq + ((size_t)b * S_DIM + idx_s[rowA0]) * D_DIM + kcA;
    const float* aPtr1 = seq + ((size_t)b * S_DIM + idx_s[rowA1]) * D_DIM + kcA;

    // B-tile load tasks: 96 n x 8 chunks = 768 tasks, 3 per thread
    const int nB0 = tid >> 3;           // 0..31
    const int nB1 = nB0 + 32;
    const int nB2 = nB0 + 64;
    const int kcB = kcA;
    const float* bPtr0 = clsw + (size_t)nB0 * D_DIM + kcB;
    const float* bPtr1 = clsw + (size_t)nB1 * D_DIM + kcB;
    const float* bPtr2 = clsw + (size_t)nB2 * D_DIM + kcB;

    // Packed accumulators: .lo = even-k partial, .hi = odd-k partial
    ull acc[4][6];
#pragma unroll
    for (int i = 0; i < 4; i++)
#pragma unroll
        for (int j = 0; j < 6; j++) acc[i][j] = 0ull;

    for (int kt = 0; kt < D_DIM / KT; kt++) {
        const int k0 = kt * KT;
        // prefetch (overlaps previous tile's compute)
        float4 av0 = *(const float4*)(aPtr0 + k0);
        float4 av1 = *(const float4*)(aPtr1 + k0);
        float4 bv0 = *(const float4*)(bPtr0 + k0);
        float4 bv1 = *(const float4*)(bPtr1 + k0);
        float4 bv2 = *(const float4*)(bPtr2 + k0);

        __syncthreads();  // previous compute done before overwrite
        *(float4*)&As[rowA0][kcA] = av0;
        *(float4*)&As[rowA1][kcA] = av1;
        *(float4*)&Bs[nB0][kcB]   = bv0;
        *(float4*)&Bs[nB1][kcB]   = bv1;
        *(float4*)&Bs[nB2][kcB]   = bv2;
        __syncthreads();

#pragma unroll
        for (int q = 0; q < KT / 4; q++) {
            ulonglong2 a2[4];
            ulonglong2 b2[6];
#pragma unroll
            for (int i = 0; i < 4; i++)
                a2[i] = *(const ulonglong2*)&As[tc + 16 * i][q * 4];
#pragma unroll
            for (int j = 0; j < 6; j++)
                b2[j] = *(const ulonglong2*)&Bs[tr + 16 * j][q * 4];
#pragma unroll
            for (int i = 0; i < 4; i++)
#pragma unroll
                for (int j = 0; j < 6; j++) {
                    acc[i][j] = ffma2(a2[i].x, b2[j].x, acc[i][j]);
                    acc[i][j] = ffma2(a2[i].y, b2[j].y, acc[i][j]);
                }
        }
    }

    // Epilogue: out[a, b, w, c], n = a*3 + c
    const size_t BW3 = (size_t)B_DIM * W_DIM * 3;
#pragma unroll
    for (int j = 0; j < 6; j++) {
        const int n  = tr + 16 * j;
        const int a_ = n / 3;
        const int c_ = n - a_ * 3;
        const float bias = clsb[n];
        const size_t base = (size_t)a_ * BW3 + (size_t)b * (W_DIM * 3) + c_;
#pragma unroll
        for (int i = 0; i < 4; i++) {
            const int w = w0 + tc + 16 * i;
            float lo, hi;
            unpack2(acc[i][j], lo, hi);
            out[base + (size_t)w * 3] = lo + hi + bias;
        }
    }
}

extern "C" void kernel_launch(void* const* d_in, const int* in_sizes, int n_in,
                              void* d_out, int out_size) {
    const float* seq  = (const float*)d_in[0];  // [B, S, D] fp32
    const int*   widx = (const int*)d_in[1];    // [B, W] int32
    const float* clsw = (const float*)d_in[2];  // [A, 3, D] fp32 -> [96, 768]
    const float* clsb = (const float*)d_in[3];  // [A, 3] fp32 -> [96]
    float* out = (float*)d_out;                 // [A, B, W, 3] fp32

    dim3 grid(W_DIM / MT, B_DIM);  // (4, 64) = 256 CTAs
    ner_gemm_kernel<<<grid, 256>>>(seq, widx, clsw, clsb, out);
}

// round 3
// speedup vs baseline: 2.3408x; 2.3408x over previous
#include <cuda_runtime.h>
#include <cstdint>

#define B_DIM 64
#define S_DIM 512
#define W_DIM 256
#define D_DIM 768
#define N_DIM 96
#define KT 64
#define NUM_KT 12
#define THREADS 256

#define ROW_STRIDE 144              // bytes per bf16 tile row (64*2 + 16 pad)
#define OFF_AHI 0
#define OFF_ALO 18432               // 128 * 144
#define OFF_BHI 36864
#define OFF_BLO 50688               // 36864 + 96*144
#define STAGE   64512               // 50688 + 96*144
#define SM_TILES 1024
#define SMEM_TOTAL (SM_TILES + 2 * STAGE)

static __device__ __forceinline__ uint32_t smem_u32(const void* p) {
    uint32_t a;
    asm("{ .reg .u64 t; cvta.to.shared.u64 t, %1; cvt.u32.u64 %0, t; }" : "=r"(a) : "l"(p));
    return a;
}

static __device__ __forceinline__ void ldsm4(uint32_t* r, uint32_t addr) {
    asm volatile("ldmatrix.sync.aligned.m8n8.x4.shared.b16 {%0,%1,%2,%3}, [%4];"
                 : "=r"(r[0]), "=r"(r[1]), "=r"(r[2]), "=r"(r[3]) : "r"(addr));
}

static __device__ __forceinline__ void mma_bf16(float* c, const uint32_t* a, const uint32_t* b) {
    asm volatile(
        "mma.sync.aligned.m16n8k16.row.col.f32.bf16.bf16.f32 "
        "{%0,%1,%2,%3}, {%4,%5,%6,%7}, {%8,%9}, {%0,%1,%2,%3};"
        : "+f"(c[0]), "+f"(c[1]), "+f"(c[2]), "+f"(c[3])
        : "r"(a[0]), "r"(a[1]), "r"(a[2]), "r"(a[3]), "r"(b[0]), "r"(b[1]));
}

// fp32x4 -> hi bf16x2 pair + exact-ish residual lo bf16x2 pair
static __device__ __forceinline__ void cvt_split(float4 v, uint2& hi, uint2& lo) {
    uint32_t h0, h1, l0, l1;
    asm("cvt.rn.bf16x2.f32 %0, %1, %2;" : "=r"(h0) : "f"(v.y), "f"(v.x));
    asm("cvt.rn.bf16x2.f32 %0, %1, %2;" : "=r"(h1) : "f"(v.w), "f"(v.z));
    float r0 = v.x - __uint_as_float(h0 << 16);
    float r1 = v.y - __uint_as_float(h0 & 0xffff0000u);
    float r2 = v.z - __uint_as_float(h1 << 16);
    float r3 = v.w - __uint_as_float(h1 & 0xffff0000u);
    asm("cvt.rn.bf16x2.f32 %0, %1, %2;" : "=r"(l0) : "f"(r1), "f"(r0));
    asm("cvt.rn.bf16x2.f32 %0, %1, %2;" : "=r"(l1) : "f"(r3), "f"(r2));
    hi.x = h0; hi.y = h1; lo.x = l0; lo.y = l1;
}

__global__ __launch_bounds__(THREADS, 1)
void ner_hmma_kernel(const float* __restrict__ seq, const int* __restrict__ widx,
                     const float* __restrict__ clsw, const float* __restrict__ clsb,
                     float* __restrict__ out) {
    extern __shared__ char smem[];
    const uint32_t sb = smem_u32(smem);
    const int tid  = threadIdx.x;
    const int wid  = tid >> 5;
    const int lane = tid & 31;
    const int b  = blockIdx.x >> 1;
    const int w0 = (blockIdx.x & 1) << 7;

    int* idx_s = (int*)smem;
    if (tid < 128) idx_s[tid] = widx[b * W_DIM + w0 + tid];
    __syncthreads();

    // ---- producer mapping: row-chunk pr, float4 k-chunk pk ----
    const int pr = tid >> 4;           // 0..15
    const int pk = (tid & 15) << 2;    // float idx 0..60

    const float* aP[8];
#pragma unroll
    for (int i = 0; i < 8; i++)
        aP[i] = seq + ((size_t)b * S_DIM + idx_s[pr + 16 * i]) * D_DIM + pk;
    const float* bP[6];
#pragma unroll
    for (int i = 0; i < 6; i++)
        bP[i] = clsw + (size_t)(pr + 16 * i) * D_DIM + pk;

    uint32_t soA[8], soB[6];
#pragma unroll
    for (int i = 0; i < 8; i++) soA[i] = (uint32_t)(pr + 16 * i) * ROW_STRIDE + (uint32_t)pk * 2;
#pragma unroll
    for (int i = 0; i < 6; i++) soB[i] = (uint32_t)(pr + 16 * i) * ROW_STRIDE + (uint32_t)pk * 2;

    // ---- consumer mapping ----
    const int wm = (wid & 3) * 32;     // row base of warp
    const int wn = (wid >> 2) * 48;    // col base of warp

    // A ldmatrix lane addressing: m = lane&15, k-half = lane>>4 (16B)
    const uint32_t aOff = (uint32_t)(wm + (lane & 15)) * ROW_STRIDE + ((lane >> 4) << 4);
    // B ldmatrix lane addressing: n = ((lane>>4)<<3)+(lane&7), k-half = (lane>>3)&1
    const uint32_t bOff = (uint32_t)(wn + ((lane >> 4) << 3) + (lane & 7)) * ROW_STRIDE
                        + (((lane >> 3) & 1) << 4);

    float acc[12][4];
#pragma unroll
    for (int i = 0; i < 12; i++)
#pragma unroll
        for (int v = 0; v < 4; v++) acc[i][v] = 0.f;

    // prefetch tile 0
    float4 ra[8], rb[6];
#pragma unroll
    for (int i = 0; i < 8; i++) ra[i] = *(const float4*)(aP[i]);
#pragma unroll
    for (int i = 0; i < 6; i++) rb[i] = *(const float4*)(bP[i]);

    for (int t = 0; t < NUM_KT; t++) {
        const int p = t & 1;
        char* buf = smem + SM_TILES + p * STAGE;

        // store + convert current tile
#pragma unroll
        for (int i = 0; i < 8; i++) {
            uint2 hi, lo;
            cvt_split(ra[i], hi, lo);
            *(uint2*)(buf + OFF_AHI + soA[i]) = hi;
            *(uint2*)(buf + OFF_ALO + soA[i]) = lo;
        }
#pragma unroll
        for (int i = 0; i < 6; i++) {
            uint2 hi, lo;
            cvt_split(rb[i], hi, lo);
            *(uint2*)(buf + OFF_BHI + soB[i]) = hi;
            *(uint2*)(buf + OFF_BLO + soB[i]) = lo;
        }

        // prefetch next tile (overlaps with compute below)
        if (t + 1 < NUM_KT) {
            const int kg = (t + 1) * KT;
#pragma unroll
            for (int i = 0; i < 8; i++) ra[i] = *(const float4*)(aP[i] + kg);
#pragma unroll
            for (int i = 0; i < 6; i++) rb[i] = *(const float4*)(bP[i] + kg);
        }
        __syncthreads();

        const uint32_t sbuf = sb + SM_TILES + p * STAGE;
#pragma unroll
        for (int ks = 0; ks < 4; ks++) {
            const uint32_t k0b = (uint32_t)ks * 32;  // 16 bf16 = 32 B
            uint32_t ah[2][4], al[2][4];
#pragma unroll
            for (int i = 0; i < 2; i++) {
                ldsm4(ah[i], sbuf + OFF_AHI + aOff + i * (16 * ROW_STRIDE) + k0b);
                ldsm4(al[i], sbuf + OFF_ALO + aOff + i * (16 * ROW_STRIDE) + k0b);
            }
            uint32_t bh[3][4], bl[3][4];
#pragma unroll
            for (int j = 0; j < 3; j++) {
                ldsm4(bh[j], sbuf + OFF_BHI + bOff + j * (16 * ROW_STRIDE) + k0b);
                ldsm4(bl[j], sbuf + OFF_BLO + bOff + j * (16 * ROW_STRIDE) + k0b);
            }
#pragma unroll
            for (int i = 0; i < 2; i++)
#pragma unroll
                for (int j = 0; j < 6; j++) {
                    const uint32_t* bhf = &bh[j >> 1][(j & 1) * 2];
                    const uint32_t* blf = &bl[j >> 1][(j & 1) * 2];
                    mma_bf16(acc[i * 6 + j], ah[i], bhf);
                    mma_bf16(acc[i * 6 + j], ah[i], blf);
                    mma_bf16(acc[i * 6 + j], al[i], bhf);
                }
        }
        __syncthreads();
    }

    // ---- epilogue: scatter to out[a, b, w, c] ----
#pragma unroll
    for (int i = 0; i < 2; i++) {
#pragma unroll
        for (int j = 0; j < 6; j++) {
            const float* c = acc[i * 6 + j];
            const int n_base = wn + j * 8 + 2 * (lane & 3);
            const int m_base = wm + i * 16 + (lane >> 2);
#pragma unroll
            for (int v = 0; v < 4; v++) {
                const int n = n_base + (v & 1);
                const int m = m_base + (v >> 1) * 8;
                const int w = w0 + m;
                const int a_ = n / 3;
                const int c_ = n - a_ * 3;
                out[(size_t)a_ * (B_DIM * W_DIM * 3) + (size_t)b * (W_DIM * 3) + w * 3 + c_]
                    = c[v] + clsb[n];
            }
        }
    }
}

extern "C" void kernel_launch(void* const* d_in, const int* in_sizes, int n_in,
                              void* d_out, int out_size) {
    const float* seq  = (const float*)d_in[0];  // [B, S, D] fp32
    const int*   widx = (const int*)d_in[1];    // [B, W] int32
    const float* clsw = (const float*)d_in[2];  // [A*3, D] fp32
    const float* clsb = (const float*)d_in[3];  // [A*3] fp32
    float* out = (float*)d_out;                 // [A, B, W, 3] fp32

    cudaFuncSetAttribute(ner_hmma_kernel, cudaFuncAttributeMaxDynamicSharedMemorySize, SMEM_TOTAL);
    ner_hmma_kernel<<<128, THREADS, SMEM_TOTAL>>>(seq, widx, clsw, clsb, out);
}